// round 1
// baseline (speedup 1.0000x reference)
#include <cuda_runtime.h>
#include <math.h>

#define NB    256
#define NPB   65536          // pixels per batch (H*W)
#define NBATCH 4
#define EPS   1e-10f

// ---------------- scratch (no allocations allowed) ----------------
__device__ float g_joint[NBATCH * NB * NB];   // 1 MB
__device__ float g_h1[NBATCH * NB];
__device__ float g_h2[NBATCH * NB];
__device__ float g_mi[NBATCH];

// ---------------- kernel 1: zero scratch ----------------
__global__ void mi_zero_kernel() {
    int idx = blockIdx.x * blockDim.x + threadIdx.x;
    int stride = gridDim.x * blockDim.x;
    for (int i = idx; i < NBATCH * NB * NB; i += stride) g_joint[i] = 0.0f;
    if (idx < NBATCH * NB) { g_h1[idx] = 0.0f; g_h2[idx] = 0.0f; }
    if (idx < NBATCH) g_mi[idx] = 0.0f;
}

// ---------------- kernel 2: sparse KDE accumulation ----------------
// Each CTA handles PIX_PER_CTA consecutive pixels (all in one batch).
// Per pixel: weights on the two straddling bins (others are <= e^-50 relative).
#define THREADS_ACC 256
#define PIX_PER_CTA 1024     // THREADS_ACC * 4 (float4 per thread)

__global__ __launch_bounds__(THREADS_ACC)
void mi_accum_kernel(const float* __restrict__ in1, const float* __restrict__ in2) {
    __shared__ float sh1[NB];
    __shared__ float sh2[NB];
    int tid = threadIdx.x;
    if (tid < NB) { sh1[tid] = 0.0f; sh2[tid] = 0.0f; }
    __syncthreads();

    int base = blockIdx.x * PIX_PER_CTA;          // pixel index
    int b = base / NPB;                           // batch of this CTA
    float* __restrict__ joint = g_joint + b * NB * NB;

    const float4* __restrict__ v1 = (const float4*)(in1 + base);
    const float4* __restrict__ v2 = (const float4*)(in2 + base);
    float4 a = v1[tid];
    float4 c = v2[tid];

    const float xs1[4] = {a.x, a.y, a.z, a.w};
    const float xs2[4] = {c.x, c.y, c.z, c.w};

#pragma unroll
    for (int k = 0; k < 4; k++) {
        float x1 = xs1[k] * 255.0f;
        float x2 = xs2[k] * 255.0f;
        int i0 = min((int)floorf(x1), NB - 2);
        int j0 = min((int)floorf(x2), NB - 2);
        float f1 = x1 - (float)i0, g1 = 1.0f - f1;
        float f2 = x2 - (float)j0, g2 = 1.0f - f2;
        float wa1 = __expf(-50.0f * f1 * f1);
        float wb1 = __expf(-50.0f * g1 * g1);
        float wa2 = __expf(-50.0f * f2 * f2);
        float wb2 = __expf(-50.0f * g2 * g2);

        atomicAdd(&sh1[i0],     wa1);
        atomicAdd(&sh1[i0 + 1], wb1);
        atomicAdd(&sh2[j0],     wa2);
        atomicAdd(&sh2[j0 + 1], wb2);

        float* row = joint + i0 * NB + j0;
        atomicAdd(row,          wa1 * wa2);
        atomicAdd(row + 1,      wa1 * wb2);
        atomicAdd(row + NB,     wb1 * wa2);
        atomicAdd(row + NB + 1, wb1 * wb2);
    }

    __syncthreads();
    if (tid < NB) {
        atomicAdd(&g_h1[b * NB + tid], sh1[tid]);
        atomicAdd(&g_h2[b * NB + tid], sh2[tid]);
    }
}

// ---------------- kernel 3: per-batch entropies + MI ----------------
__device__ __forceinline__ float block_reduce_1024(float v, float* sred) {
#pragma unroll
    for (int o = 16; o; o >>= 1) v += __shfl_xor_sync(0xffffffffu, v, o);
    int wid = threadIdx.x >> 5, lid = threadIdx.x & 31;
    if (lid == 0) sred[wid] = v;
    __syncthreads();
    float r = 0.0f;
    if (threadIdx.x < 32) {
        r = sred[threadIdx.x];
#pragma unroll
        for (int o = 16; o; o >>= 1) r += __shfl_xor_sync(0xffffffffu, r, o);
        if (threadIdx.x == 0) sred[0] = r;
    }
    __syncthreads();
    float out = sred[0];
    __syncthreads();
    return out;
}

__global__ __launch_bounds__(1024)
void mi_reduce_kernel() {
    __shared__ float sred[32];
    int b = blockIdx.x;
    int tid = threadIdx.x;
    const float* __restrict__ h1 = g_h1 + b * NB;
    const float* __restrict__ h2 = g_h2 + b * NB;
    const float* __restrict__ joint = g_joint + b * NB * NB;

    const float invN = 1.0f / (float)NPB;

    // marginal sums
    float s1p = 0.0f, s2p = 0.0f;
    if (tid < NB) { s1p = h1[tid]; s2p = h2[tid]; }
    float S1 = block_reduce_1024(s1p, sred);
    float S2 = block_reduce_1024(s2p, sred);
    float d1 = S1 * invN + EPS;
    float d2 = S2 * invN + EPS;

    // marginal entropies
    float e1p = 0.0f, e2p = 0.0f;
    if (tid < NB) {
        float p = (h1[tid] * invN) / d1;
        float q = (h2[tid] * invN) / d2;
        e1p = p * __log2f(p + EPS);
        e2p = q * __log2f(q + EPS);
    }
    float H1 = -block_reduce_1024(e1p, sred);
    float H2 = -block_reduce_1024(e2p, sred);

    // joint sum (double per-thread accumulation for safety)
    double sjd = 0.0;
    for (int i = tid; i < NB * NB; i += 1024) sjd += (double)joint[i];
    float Sj = block_reduce_1024((float)sjd, sred) + EPS;
    float inv = 1.0f / Sj;

    // joint entropy
    double ejd = 0.0;
    for (int i = tid; i < NB * NB; i += 1024) {
        float q = joint[i] * inv;
        ejd += (double)(q * __log2f(q + EPS));
    }
    float Hj = -block_reduce_1024((float)ejd, sred);

    if (tid == 0) {
        float mi = H1 + H2 - Hj;
        g_mi[b] = 2.0f * mi / (H1 + H2);
    }
}

// ---------------- kernel 4: combine ----------------
__global__ void mi_final_kernel(float* out) {
    if (threadIdx.x == 0 && blockIdx.x == 0) {
        out[0] = 0.25f * (g_mi[0] + g_mi[1] + g_mi[2] + g_mi[3]);
    }
}

// ---------------- launch ----------------
extern "C" void kernel_launch(void* const* d_in, const int* in_sizes, int n_in,
                              void* d_out, int out_size) {
    const float* in1 = (const float*)d_in[0];
    const float* in2 = (const float*)d_in[1];
    float* out = (float*)d_out;

    mi_zero_kernel<<<1024, 256>>>();

    int total_pix = NBATCH * NPB;                 // 262144
    int grid_acc = total_pix / PIX_PER_CTA;       // 256
    mi_accum_kernel<<<grid_acc, THREADS_ACC>>>(in1, in2);

    mi_reduce_kernel<<<NBATCH, 1024>>>();

    mi_final_kernel<<<1, 32>>>(out);
}

// round 2
// speedup vs baseline: 1.4362x; 1.4362x over previous
#include <cuda_runtime.h>
#include <math.h>

#define NB     256
#define NPB    65536          // pixels per batch (H*W)
#define NBATCH 4
#define EPS    1e-10f
#define INV_N  (1.0f / 65536.0f)

// ---------------- persistent scratch (zero-init at module load; each call
// leaves everything re-zeroed, so replays are deterministic) ----------------
__device__ float  g_joint[NBATCH * NB * NB];   // 1 MB
__device__ float  g_h1[NBATCH * NB];
__device__ float  g_h2[NBATCH * NB];
__device__ double g_sj[NBATCH];                // joint sum partials
__device__ double g_ej[NBATCH];                // sum j*log2(j+eps) partials
__device__ float  g_H1[NBATCH], g_H2[NBATCH];
__device__ unsigned g_bar;                     // last-block ticket

// ================= kernel 1: sparse KDE accumulation =================
// sigma=0.1 in bin units (bins 1.0 apart): weight on bins beyond the two
// straddling ones is <= e^-50 ~ 2e-22 relative -> truncate to 2 bins.
#define THREADS_ACC 256
#define PIX_PER_CTA 1024     // THREADS_ACC * 4 (one float4 per thread)

__global__ __launch_bounds__(THREADS_ACC)
void mi_accum_kernel(const float* __restrict__ in1, const float* __restrict__ in2) {
    __shared__ float sh1[NB];
    __shared__ float sh2[NB];
    int tid = threadIdx.x;
    if (tid < NB) { sh1[tid] = 0.0f; sh2[tid] = 0.0f; }
    __syncthreads();

    int base = blockIdx.x * PIX_PER_CTA;          // pixel index
    int b = base / NPB;                           // batch of this CTA
    float* __restrict__ joint = g_joint + b * NB * NB;

    const float4* __restrict__ v1 = (const float4*)(in1 + base);
    const float4* __restrict__ v2 = (const float4*)(in2 + base);
    float4 a = v1[tid];
    float4 c = v2[tid];

    const float xs1[4] = {a.x, a.y, a.z, a.w};
    const float xs2[4] = {c.x, c.y, c.z, c.w};

#pragma unroll
    for (int k = 0; k < 4; k++) {
        float x1 = xs1[k] * 255.0f;
        float x2 = xs2[k] * 255.0f;
        int i0 = min((int)floorf(x1), NB - 2);
        int j0 = min((int)floorf(x2), NB - 2);
        float f1 = x1 - (float)i0, q1 = 1.0f - f1;
        float f2 = x2 - (float)j0, q2 = 1.0f - f2;
        float wa1 = __expf(-50.0f * f1 * f1);
        float wb1 = __expf(-50.0f * q1 * q1);
        float wa2 = __expf(-50.0f * f2 * f2);
        float wb2 = __expf(-50.0f * q2 * q2);

        atomicAdd(&sh1[i0],     wa1);
        atomicAdd(&sh1[i0 + 1], wb1);
        atomicAdd(&sh2[j0],     wa2);
        atomicAdd(&sh2[j0 + 1], wb2);

        float* row = joint + i0 * NB + j0;
        atomicAdd(row,          wa1 * wa2);
        atomicAdd(row + 1,      wa1 * wb2);
        atomicAdd(row + NB,     wb1 * wa2);
        atomicAdd(row + NB + 1, wb1 * wb2);
    }

    __syncthreads();
    if (tid < NB) {
        atomicAdd(&g_h1[b * NB + tid], sh1[tid]);
        atomicAdd(&g_h2[b * NB + tid], sh2[tid]);
    }
}

// ================= kernel 2: fused reduce + final + re-zero =================
// grid = NBATCH * 16 blocks, 256 threads. Each block handles 4096 joint
// entries (single pass: sum + sum j*log2(j+eps)), zeroes them, and
// atomically accumulates per-batch partials. Block sub==0 of each batch also
// does the exact marginal entropies. The last block to arrive combines
// everything, writes d_out, and resets all cross-call state.
#define RB_PER_BATCH 16

__device__ __forceinline__ double bred256(double v, double* sred) {
#pragma unroll
    for (int o = 16; o; o >>= 1) v += __shfl_xor_sync(0xffffffffu, v, o);
    int wid = threadIdx.x >> 5, lid = threadIdx.x & 31;
    if (lid == 0) sred[wid] = v;
    __syncthreads();
    double r = 0.0;
    if (threadIdx.x < 32) {
        r = (threadIdx.x < 8) ? sred[threadIdx.x] : 0.0;
#pragma unroll
        for (int o = 4; o; o >>= 1) r += __shfl_xor_sync(0xffffffffu, r, o);
        if (threadIdx.x == 0) sred[0] = r;
    }
    __syncthreads();
    double out = sred[0];
    __syncthreads();
    return out;
}

__global__ __launch_bounds__(256)
void mi_reduce_final_kernel(float* __restrict__ out) {
    __shared__ double sred[8];
    __shared__ unsigned s_ticket;
    int tid = threadIdx.x;
    int b   = blockIdx.x / RB_PER_BATCH;
    int sub = blockIdx.x % RB_PER_BATCH;

    // ---- joint slice: 4096 floats, single pass, then zero ----
    float4* j4 = (float4*)(g_joint + b * NB * NB + sub * 4096);
    double sj = 0.0, ej = 0.0;
#pragma unroll
    for (int k = 0; k < 4; k++) {
        int idx = tid + k * 256;
        float4 j = j4[idx];
        sj += (double)j.x + (double)j.y + (double)j.z + (double)j.w;
        ej += (double)(j.x * __log2f(j.x + EPS));
        ej += (double)(j.y * __log2f(j.y + EPS));
        ej += (double)(j.z * __log2f(j.z + EPS));
        ej += (double)(j.w * __log2f(j.w + EPS));
        j4[idx] = make_float4(0.0f, 0.0f, 0.0f, 0.0f);   // re-zero for next call
    }
    sj = bred256(sj, sred);
    ej = bred256(ej, sred);
    if (tid == 0) {
        atomicAdd(&g_sj[b], sj);
        atomicAdd(&g_ej[b], ej);
    }

    // ---- marginals: exact reference math, one block per batch ----
    if (sub == 0) {
        float h1 = g_h1[b * NB + tid];
        float h2 = g_h2[b * NB + tid];
        g_h1[b * NB + tid] = 0.0f;                        // re-zero
        g_h2[b * NB + tid] = 0.0f;
        float m1 = h1 * INV_N;
        float m2 = h2 * INV_N;
        double S1 = bred256((double)m1, sred);
        double S2 = bred256((double)m2, sred);
        float p1 = m1 / ((float)S1 + EPS);
        float p2 = m2 / ((float)S2 + EPS);
        double e1 = bred256((double)(p1 * __log2f(p1 + EPS)), sred);
        double e2 = bred256((double)(p2 * __log2f(p2 + EPS)), sred);
        if (tid == 0) {
            g_H1[b] = (float)(-e1);
            g_H2[b] = (float)(-e2);
        }
    }

    // ---- last block combines + resets ----
    __threadfence();
    __syncthreads();
    if (tid == 0) s_ticket = atomicAdd(&g_bar, 1u);
    __syncthreads();
    if (s_ticket == (unsigned)(NBATCH * RB_PER_BATCH - 1)) {
        if (tid == 0) {
            __threadfence();
            double acc = 0.0;
#pragma unroll
            for (int bb = 0; bb < NBATCH; bb++) {
                double Sj = g_sj[bb];
                double Ej = g_ej[bb];
                double den = Sj + (double)EPS;
                // Hj = -sum q*log2(q+eps), q = j/(Sj+eps), factored single-pass
                double Hj = -(Ej - Sj * log2(den)) / den;
                double H1 = (double)g_H1[bb];
                double H2 = (double)g_H2[bb];
                double mi = H1 + H2 - Hj;
                acc += 2.0 * mi / (H1 + H2);
                g_sj[bb] = 0.0; g_ej[bb] = 0.0;           // reset cross-call state
                g_H1[bb] = 0.0f; g_H2[bb] = 0.0f;
            }
            out[0] = (float)(acc * 0.25);
            g_bar = 0u;
        }
    }
}

// ================= launch: exactly 2 kernels =================
extern "C" void kernel_launch(void* const* d_in, const int* in_sizes, int n_in,
                              void* d_out, int out_size) {
    const float* in1 = (const float*)d_in[0];
    const float* in2 = (const float*)d_in[1];
    float* out = (float*)d_out;

    int grid_acc = (NBATCH * NPB) / PIX_PER_CTA;       // 256
    mi_accum_kernel<<<grid_acc, THREADS_ACC>>>(in1, in2);
    mi_reduce_final_kernel<<<NBATCH * RB_PER_BATCH, 256>>>(out);
}